// round 17
// baseline (speedup 1.0000x reference)
#include <cuda_runtime.h>
#include <math.h>
#include <float.h>

#define BB 8
#define NN 4096
#define KK 9
#define NPTS (BB*NN)        /* 32768 */
#define ROWS (NPTS*KK)      /* 294912 */
#define QB 32               /* queries per block (knn) */
#define QW 4                /* queries per warp */
#define CAP 48              /* survivor capacity per query */
#define SAMPLE_ITERS 32     /* pass0 samples first 2048 candidates */
#define NBP (NPTS/QB)       /* 1024 knn/BN1 partial blocks */
#define NBF 256             /* mlp partial blocks */

typedef unsigned long long ull;

// Scratch (allocation-free: __device__ globals)
__device__ float g_rel[27*NPTS];     // SoA: [(e*3+c)*NPTS + gid], phi-sorted rows
__device__ float g_p1[NBP*20];
__device__ float g_p2[NBF*20];
__device__ float g_s1v[20];          // mu[10], inv[10]
__device__ float g_s2v[20];
__device__ float g_hmax[NPTS*10];
__device__ float g_hmin[NPTS*10];

__device__ __forceinline__ bool dless(float d1, int j1, float d2, int j2) {
    return d1 < d2 || (d1 == d2 && j1 < j2);
}

// ---- packed f32x2 helpers: two bit-identical fp32 ops per issue -----------
__device__ __forceinline__ ull pack2(float lo, float hi) {
    ull r; asm("mov.b64 %0, {%1, %2};" : "=l"(r) : "f"(lo), "f"(hi)); return r;
}
__device__ __forceinline__ void unpack2(ull v, float& lo, float& hi) {
    asm("mov.b64 {%0, %1}, %2;" : "=f"(lo), "=f"(hi) : "l"(v));
}
__device__ __forceinline__ ull fma2(ull a, ull b, ull c) {
    ull d; asm("fma.rn.f32x2 %0, %1, %2, %3;" : "=l"(d) : "l"(a), "l"(b), "l"(c));
    return d;
}
__device__ __forceinline__ ull mul2(ull a, ull b) {
    ull d; asm("mul.rn.f32x2 %0, %1, %2;" : "=l"(d) : "l"(a), "l"(b)); return d;
}

// Warp-distributed sorted insert into ascending 32-slot list (validated R4-R16).
__device__ __forceinline__ void warp_insert(float nd, int nj, float& sd, int& si,
                                            const int lane) {
    const float pd = __shfl_up_sync(0xffffffffu, sd, 1);
    const int   pi = __shfl_up_sync(0xffffffffu, si, 1);
    const bool pcur  = dless(nd, nj, sd, si);
    const bool pprev = (lane > 0) && dless(nd, nj, pd, pi);
    if (pcur) { sd = pprev ? pd : nd; si = pprev ? pi : nj; }
}

// Bitonic sort of 32 values across lanes, ascending; QW interleaved for ILP.
__device__ __forceinline__ void bitonic32_val(float e[QW], const int lane) {
    #pragma unroll
    for (int k = 2; k <= 32; k <<= 1) {
        #pragma unroll
        for (int s = k >> 1; s > 0; s >>= 1) {
            const bool keepMin = (((lane & s) == 0) == ((lane & k) == 0));
            #pragma unroll
            for (int q = 0; q < QW; ++q) {
                const float oe = __shfl_xor_sync(0xffffffffu, e[q], s);
                const bool takeOther = ((oe < e[q]) == keepMin);
                e[q] = takeOther ? oe : e[q];
            }
        }
    }
}

// Bitonic sort of 32 (d,j) pairs across lanes, ascending lex (validated R6-R16).
__device__ __forceinline__ void bitonic32_pair(float& d, int& j, const int lane) {
    #pragma unroll
    for (int k = 2; k <= 32; k <<= 1) {
        #pragma unroll
        for (int s = k >> 1; s > 0; s >>= 1) {
            const bool keepMin = (((lane & s) == 0) == ((lane & k) == 0));
            const float od = __shfl_xor_sync(0xffffffffu, d, s);
            const int   oj = __shfl_xor_sync(0xffffffffu, j, s);
            const bool takeOther = (dless(od, oj, d, j) == keepMin);
            d = takeOther ? od : d;
            j = takeOther ? oj : j;
        }
    }
}

// ---------------------------------------------------------------------------
// Kernel 1: threshold-filter kNN (R16 core) + FUSED Phase C (features +
// linear1 + BN1 partials) using the already-resident smem coordinates.
// grid (NN/QB, BB), block 256.
// ---------------------------------------------------------------------------
__global__ __launch_bounds__(256, 3) void knn_kernel(const float* __restrict__ x,
                                                     const float* __restrict__ W1,
                                                     const float* __restrict__ b1) {
    extern __shared__ float smem_f[];
    float* sxx = smem_f;            // [NN]
    float* syy = smem_f + NN;
    float* szz = smem_f + 2*NN;
    float* sww = smem_f + 3*NN;
    int* s_list = (int*)(smem_f + 4*NN);       // 8 warps * QW * CAP ints (6KB)
    int* s_nbr  = (int*)(s_list + 8*QW*CAP);   // QB*9 ints
    // Phase C overlays the dead s_list region (re-used after a barrier):
    float* s_ph = (float*)s_list;              // QB*9
    float* s_rx = s_ph + QB*9;                 // QB*9
    float* s_ry = s_rx + QB*9;                 // QB*9
    float* s_rz = s_ry + QB*9;                 // QB*9  (total 4.6KB <= 6KB)
    __shared__ float sW1[100], sb1[10], s_sg[QB], sred[8*20];

    const int tid = threadIdx.x;
    const int lane = tid & 31;
    const int w = tid >> 5;
    const int b = blockIdx.y;
    const float* xb = x + (size_t)b * NN * 3;

    if (tid < 100) sW1[tid] = W1[tid];
    if (tid < 10)  sb1[tid] = b1[tid];
    for (int j = tid; j < NN; j += blockDim.x) {
        float xx = xb[j*3+0], yy = xb[j*3+1], zz = xb[j*3+2];
        sxx[j] = xx; syy[j] = yy; szz[j] = zz;
        sww[j] = fmaf(zz, zz, fmaf(yy, yy, xx*xx));
    }
    __syncthreads();

    int* list = s_list + w * (QW * CAP);

    const int n0 = blockIdx.x * QB + w * QW;
    float qx[QW], qy[QW], qz[QW];
    ull qx2[QW], qy2[QW], qz2[QW];
    #pragma unroll
    for (int q = 0; q < QW; ++q) {
        qx[q] = sxx[n0+q]; qy[q] = syy[n0+q]; qz[q] = szz[n0+q];
        qx2[q] = pack2(qx[q], qx[q]);
        qy2[q] = pack2(qy[q], qy[q]);
        qz2[q] = pack2(qz[q], qz[q]);
    }
    const ull negtwo2 = pack2(-2.0f, -2.0f);

    // --- Pass 0 (SAMPLED, sound: T >= true 10th regardless of sample) -----
    float eL[QW], eH[QW];
    #pragma unroll
    for (int q = 0; q < QW; ++q) { eL[q] = FLT_MAX; eH[q] = FLT_MAX; }
    for (int i = 0; i < SAMPLE_ITERS; ++i) {
        const int j0 = i * 64 + 2 * lane;
        const ull cx2 = *(const ull*)&sxx[j0];
        const ull cy2 = *(const ull*)&syy[j0];
        const ull cz2 = *(const ull*)&szz[j0];
        const ull cw2 = *(const ull*)&sww[j0];
        #pragma unroll
        for (int q = 0; q < QW; ++q) {
            ull dot2 = fma2(qz2[q], cz2, fma2(qy2[q], cy2, mul2(qx2[q], cx2)));
            ull ec2 = fma2(negtwo2, dot2, cw2);
            float e0, e1; unpack2(ec2, e0, e1);
            eL[q] = fminf(eL[q], e0);
            eH[q] = fminf(eH[q], e1);
        }
    }
    float m[QW];
    #pragma unroll
    for (int q = 0; q < QW; ++q) m[q] = fminf(eL[q], eH[q]);

    bitonic32_val(m, lane);
    float Tq[QW];
    #pragma unroll
    for (int q = 0; q < QW; ++q) {
        const float t = __shfl_sync(0xffffffffu, m[q], 9);
        Tq[q] = t + 1e-3f + 1e-5f * fabsf(t);
    }

    // --- Pass 1: packed filter over ALL 4096 + compact survivors ----------
    int cnt[QW];
    #pragma unroll
    for (int q = 0; q < QW; ++q) cnt[q] = 0;
    for (int i = 0; i < 64; ++i) {
        const int j0 = i * 64 + 2 * lane;
        const ull cx2 = *(const ull*)&sxx[j0];
        const ull cy2 = *(const ull*)&syy[j0];
        const ull cz2 = *(const ull*)&szz[j0];
        const ull cw2 = *(const ull*)&sww[j0];
        #pragma unroll
        for (int q = 0; q < QW; ++q) {
            ull dot2 = fma2(qz2[q], cz2, fma2(qy2[q], cy2, mul2(qx2[q], cx2)));
            ull ec2 = fma2(negtwo2, dot2, cw2);
            float e0, e1; unpack2(ec2, e0, e1);
            const bool k0 = e0 <= Tq[q];
            const bool k1 = e1 <= Tq[q];
            const unsigned b0 = __ballot_sync(0xffffffffu, k0);
            const unsigned b1 = __ballot_sync(0xffffffffu, k1);
            if (b0 | b1) {
                const unsigned lt = (1u << lane) - 1u;
                int pos = cnt[q] + __popc(b0 & lt);
                if (k0 && pos < CAP) list[q*CAP + pos] = j0;
                cnt[q] += __popc(b0);
                pos = cnt[q] + __popc(b1 & lt);
                if (k1 && pos < CAP) list[q*CAP + pos] = j0 + 1;
                cnt[q] += __popc(b1);
            }
        }
    }

    // --- Pass 2: exact d (reference formula) on survivors -----------------
    #pragma unroll
    for (int q = 0; q < QW; ++q) {
        const float q2 = sww[n0 + q];
        int resj;
        if (cnt[q] <= 32) {
            const bool v = lane < cnt[q];
            int jj = v ? list[q*CAP + lane] : 0x7fffffff;
            float dd = FLT_MAX;
            if (v) {
                const float cxx = sxx[jj], cyy = syy[jj], czz = szz[jj], cww = sww[jj];
                float dot = fmaf(qz[q], czz, fmaf(qy[q], cyy, qx[q] * cxx));
                // match reference: (x2n + x2m) - 2*dot, no fma contraction
                dd = __fsub_rn(__fadd_rn(q2, cww), __fmul_rn(2.0f, dot));
            }
            bitonic32_pair(dd, jj, lane);
            resj = jj;
        } else if (cnt[q] <= CAP) {
            // middle path: sort first 32, sorted-insert the rest
            int jj = list[q*CAP + lane];
            float dd;
            {
                const float cxx = sxx[jj], cyy = syy[jj], czz = szz[jj], cww = sww[jj];
                float dot = fmaf(qz[q], czz, fmaf(qy[q], cyy, qx[q] * cxx));
                dd = __fsub_rn(__fadd_rn(q2, cww), __fmul_rn(2.0f, dot));
            }
            bitonic32_pair(dd, jj, lane);
            for (int s = 32; s < cnt[q]; ++s) {
                const int nj = list[q*CAP + s];
                const float cxx = sxx[nj], cyy = syy[nj], czz = szz[nj], cww = sww[nj];
                float dot = fmaf(qz[q], czz, fmaf(qy[q], cyy, qx[q] * cxx));
                const float nd = __fsub_rn(__fadd_rn(q2, cww), __fmul_rn(2.0f, dot));
                warp_insert(nd, nj, dd, jj, lane);
            }
            resj = jj;
        } else {
            // fallback (P ~ 0): exact R4 ballot scan
            float sd = FLT_MAX; int si = 0x7fffffff;
            float thr_d = FLT_MAX; int thr_j = 0x7fffffff;
            for (int j0 = 0; j0 < NN; j0 += 32) {
                const int j = j0 + lane;
                const float cxx = sxx[j], cyy = syy[j], czz = szz[j], cww = sww[j];
                float dot = fmaf(qz[q], czz, fmaf(qy[q], cyy, qx[q] * cxx));
                float d = __fsub_rn(__fadd_rn(q2, cww), __fmul_rn(2.0f, dot));
                unsigned mask = __ballot_sync(0xffffffffu, dless(d, j, thr_d, thr_j));
                while (mask) {
                    const int src = __ffs(mask) - 1;
                    mask &= mask - 1;
                    const float nd = __shfl_sync(0xffffffffu, d, src);
                    const int   nj = j0 + src;
                    warp_insert(nd, nj, sd, si, lane);
                    thr_d = __shfl_sync(0xffffffffu, sd, 9);
                    thr_j = __shfl_sync(0xffffffffu, si, 9);
                }
            }
            resj = si;
        }
        // slots 1..9 = neighbors (slot 0 = self/nearest) -> smem for Phase C
        if (lane >= 1 && lane < 10) {
            s_nbr[(w * QW + q) * 9 + (lane - 1)] = resj;
        }
    }
    __syncthreads();   // s_nbr complete; s_list dead -> Phase C overlays it

    // ================= Phase C: features + linear1 + BN1 ===================
    // 8 threads per query: thread pe handles sorted row pe (pe==0 also row 8).
    const int pq = tid >> 3;          // 0..31
    const int pe = tid & 7;           // 0..7
    const int n = blockIdx.x * QB + pq;
    const int gid = b * NN + n;
    const float qxx = sxx[n], qyy = syy[n], qzz = szz[n];

    #pragma unroll
    for (int r = pe; r < 9; r += 8) {            // pe, and 8 for pe==0
        const int idx = s_nbr[pq*9 + r];
        const float rxv = sxx[idx] - qxx;
        const float ryv = syy[idx] - qyy;
        const float rzv = szz[idx] - qzz;
        s_rx[pq*9 + r] = rxv;
        s_ry[pq*9 + r] = ryv;
        s_rz[pq*9 + r] = rzv;
        s_ph[pq*9 + r] = atan2f(ryv, rxv);
    }
    __syncthreads();

    // per-thread stable sort ORDER (same comparison sequence as reference;
    // index-tracking bubble == payload bubble permutation, validated R13)
    float pha[9]; int od[9];
    #pragma unroll
    for (int u = 0; u < 9; ++u) { pha[u] = s_ph[pq*9 + u]; od[u] = u; }
    #pragma unroll
    for (int p = 0; p < 8; ++p) {
        #pragma unroll
        for (int u = 0; u < 8; ++u) {
            if (pha[u+1] < pha[u]) {
                float t = pha[u]; pha[u] = pha[u+1]; pha[u+1] = t;
                int ti = od[u]; od[u] = od[u+1]; od[u+1] = ti;
            }
        }
    }
    // sgn from sorted rows 0,1 (exact feat_row e==0 op order)
    if (pe == 0) {
        const int i1 = od[0], i2 = od[1];
        const float ax = s_rx[pq*9+i1], ay = s_ry[pq*9+i1], az = s_rz[pq*9+i1];
        const float bx = s_rx[pq*9+i2], by = s_ry[pq*9+i2], bz = s_rz[pq*9+i2];
        float nx = ay*bz - az*by;
        float ny = az*bx - ax*bz;
        float nz = ax*by - ay*bx;
        float nnv = sqrtf(nx*nx + ny*ny + nz*nz);
        float ri = 1.0f / (nnv + 1e-6f);
        nx *= ri; (void)ny; (void)nz;
        s_sg[pq] = (nx > 0.0f) ? 1.0f : -1.0f;
    }
    __syncthreads();
    const float sgn = s_sg[pq];

    float ls[10], ls2[10];
    #pragma unroll
    for (int o = 0; o < 10; ++o) { ls[o] = 0.0f; ls2[o] = 0.0f; }

    #pragma unroll
    for (int r = pe; r < 9; r += 8) {
        const int r2 = (r + 1 == 9) ? 0 : r + 1;
        const int i1 = od[r], i2 = od[r2];
        const float ax = s_rx[pq*9+i1], ay = s_ry[pq*9+i1], az = s_rz[pq*9+i1];
        const float bx = s_rx[pq*9+i2], by = s_ry[pq*9+i2], bz = s_rz[pq*9+i2];
        // geometry (exact validated op order; sgn pre-applied)
        float cx = 0.5f * (ax + bx), cy = 0.5f * (ay + by), cz = 0.5f * (az + bz);
        float nx = ay*bz - az*by;
        float ny = az*bx - ax*bz;
        float nz = ax*by - ay*bx;
        float nnv = sqrtf(nx*nx + ny*ny + nz*nz);
        float ri = 1.0f / (nnv + 1e-6f);
        nx *= ri; ny *= ri; nz *= ri;
        nx *= sgn; ny *= sgn; nz *= sgn;
        float pos = (nx*cx + ny*cy + nz*cz) / sqrtf(3.0f);
        float dv = ax*bx + ay*by + az*bz;
        float nA = sqrtf(ax*ax + ay*ay + az*az);
        float nB = sqrtf(bx*bx + by*by + bz*bz);
        float cv = dv / (nA * nB + 1e-8f);
        cv = fminf(1.0f, fmaxf(-1.0f, cv));
        float ang = acosf(cv);
        float f[10] = {cx, cy, cz, nx, ny, nz, pos, ang, nA, nB};

        // sorted rel row r -> g_rel (for mlp)
        g_rel[(3*r+0)*NPTS + gid] = ax;
        g_rel[(3*r+1)*NPTS + gid] = ay;
        g_rel[(3*r+2)*NPTS + gid] = az;

        #pragma unroll
        for (int o = 0; o < 10; ++o) {
            float h = sb1[o];
            #pragma unroll
            for (int i = 0; i < 10; ++i) h = fmaf(f[i], sW1[o*10+i], h);
            ls[o] += h;
            ls2[o] = fmaf(h, h, ls2[o]);
        }
    }

    // block reduction of BN1 partials (8 warps)
    #pragma unroll
    for (int t = 0; t < 20; ++t) {
        float v = (t < 10) ? ls[t] : ls2[t-10];
        #pragma unroll
        for (int off = 16; off > 0; off >>= 1) v += __shfl_down_sync(0xffffffffu, v, off);
        if (lane == 0) sred[w*20 + t] = v;
    }
    __syncthreads();
    if (tid < 20) {
        float s = 0.0f;
        #pragma unroll
        for (int ww = 0; ww < 8; ++ww) s += sred[ww*20 + tid];
        g_p1[(blockIdx.y * gridDim.x + blockIdx.x) * 20 + tid] = s;
    }
}

// ---------------------------------------------------------------------------
// Stats kernel: <<<1,640>>>, warp-per-column. part[nb*20] -> mu, inv.
// ---------------------------------------------------------------------------
__global__ void stats_kernel(int which, int nb) {
    const float* part = which ? g_p2 : g_p1;
    float* outv = which ? g_s2v : g_s1v;
    __shared__ double sums[20];
    const int w = threadIdx.x >> 5, lane = threadIdx.x & 31;
    if (w < 20) {
        double s = 0.0;
        for (int i = lane; i < nb; i += 32) s += (double)part[i*20 + w];
        #pragma unroll
        for (int off = 16; off > 0; off >>= 1)
            s += __shfl_down_sync(0xffffffffu, s, off);
        if (lane == 0) sums[w] = s;
    }
    __syncthreads();
    if (threadIdx.x < 10) {
        const int t = threadIdx.x;
        const float mu = (float)(sums[t] / (double)ROWS);
        const float m2 = (float)(sums[t+10] / (double)ROWS);
        const float var = fmaxf(m2 - mu*mu, 0.0f);
        outv[t] = mu;
        outv[10+t] = rsqrtf(var + 1e-5f);
    }
}

// Compute feature row e from sorted rel (identical fp-ops; R12-validated).
__device__ __forceinline__ void feat_row(const float rx[9], const float ry[9],
                                         const float rz[9], int e, float& sgn,
                                         float f[10]) {
    const int e2 = (e + 1 == 9) ? 0 : e + 1;
    float ax = rx[e],  ay = ry[e],  az = rz[e];
    float bx = rx[e2], by = ry[e2], bz = rz[e2];
    float cx = 0.5f * (ax + bx), cy = 0.5f * (ay + by), cz = 0.5f * (az + bz);
    float nx = ay*bz - az*by;
    float ny = az*bx - ax*bz;
    float nz = ax*by - ay*bx;
    float nnv = sqrtf(nx*nx + ny*ny + nz*nz);
    float ri = 1.0f / (nnv + 1e-6f);
    nx *= ri; ny *= ri; nz *= ri;
    if (e == 0) sgn = (nx > 0.0f) ? 1.0f : -1.0f;
    nx *= sgn; ny *= sgn; nz *= sgn;
    float pos = (nx*cx + ny*cy + nz*cz) / sqrtf(3.0f);
    float dv = ax*bx + ay*by + az*bz;
    float nA = sqrtf(ax*ax + ay*ay + az*az);
    float nB = sqrtf(bx*bx + by*by + bz*bz);
    float cv = dv / (nA * nB + 1e-8f);
    cv = fminf(1.0f, fmaxf(-1.0f, cv));
    float ang = acosf(cv);
    f[0]=cx; f[1]=cy; f[2]=cz; f[3]=nx; f[4]=ny; f[5]=nz;
    f[6]=pos; f[7]=ang; f[8]=nA; f[9]=nB;
}

// ---------------------------------------------------------------------------
// Kernel 2: BN1+ReLU+linear2 from stored rel; per-point hmax/hmin + BN2
// partials. <<<NBF,128>>>, thread per point. (EXACT R12/R16 — accepted.)
// ---------------------------------------------------------------------------
__global__ __launch_bounds__(128) void mlp_kernel(const float* __restrict__ g1v,
                                                  const float* __restrict__ be1,
                                                  const float* __restrict__ W1,
                                                  const float* __restrict__ b1,
                                                  const float* __restrict__ W2,
                                                  const float* __restrict__ b2) {
    __shared__ float sstat[20];
    __shared__ float sW1[100], sb1[10], sW2[100], sb2[10], sg1[10], sbe1[10];
    __shared__ float sred[4*20];
    const int tid = threadIdx.x;
    if (tid < 100) { sW1[tid] = W1[tid]; sW2[tid] = W2[tid]; }
    if (tid < 20) sstat[tid] = g_s1v[tid];
    if (tid < 10) { sb1[tid] = b1[tid]; sb2[tid] = b2[tid];
                    sg1[tid] = g1v[tid]; sbe1[tid] = be1[tid]; }
    __syncthreads();

    const int gid = blockIdx.x * blockDim.x + tid;
    float rx[9], ry[9], rz[9];
    #pragma unroll
    for (int e = 0; e < 9; ++e) {
        rx[e] = g_rel[(3*e+0)*NPTS + gid];
        ry[e] = g_rel[(3*e+1)*NPTS + gid];
        rz[e] = g_rel[(3*e+2)*NPTS + gid];
    }

    float ls[10], ls2[10], hmax[10], hmin[10];
    #pragma unroll
    for (int o = 0; o < 10; ++o) {
        ls[o] = 0.0f; ls2[o] = 0.0f; hmax[o] = -FLT_MAX; hmin[o] = FLT_MAX;
    }
    float sgn = 1.0f;
    #pragma unroll
    for (int e = 0; e < 9; ++e) {
        float f[10];
        feat_row(rx, ry, rz, e, sgn, f);
        float a[10];
        #pragma unroll
        for (int o = 0; o < 10; ++o) {
            float h = sb1[o];
            #pragma unroll
            for (int i = 0; i < 10; ++i) h = fmaf(f[i], sW1[o*10+i], h);
            h = ((h - sstat[o]) * sstat[10+o]) * sg1[o] + sbe1[o];
            a[o] = fmaxf(h, 0.0f);
        }
        #pragma unroll
        for (int o = 0; o < 10; ++o) {
            float h = sb2[o];
            #pragma unroll
            for (int i = 0; i < 10; ++i) h = fmaf(a[i], sW2[o*10+i], h);
            ls[o] += h;
            ls2[o] = fmaf(h, h, ls2[o]);
            hmax[o] = fmaxf(hmax[o], h);
            hmin[o] = fminf(hmin[o], h);
        }
    }
    #pragma unroll
    for (int o = 0; o < 10; ++o) {
        g_hmax[gid*10 + o] = hmax[o];
        g_hmin[gid*10 + o] = hmin[o];
    }

    const int lane = tid & 31, wid = tid >> 5;
    #pragma unroll
    for (int t = 0; t < 20; ++t) {
        float v = (t < 10) ? ls[t] : ls2[t-10];
        #pragma unroll
        for (int off = 16; off > 0; off >>= 1) v += __shfl_down_sync(0xffffffffu, v, off);
        if (lane == 0) sred[wid*20 + t] = v;
    }
    __syncthreads();
    if (tid < 20) {
        float s = 0.0f;
        #pragma unroll
        for (int ww = 0; ww < 4; ++ww) s += sred[ww*20 + tid];
        g_p2[blockIdx.x * 20 + tid] = s;
    }
}

// ---------------------------------------------------------------------------
// Kernel 3: monotone max trick + BN2 + ReLU. <<<NPTS/128,128>>> (EXACT R12.)
// ---------------------------------------------------------------------------
__global__ __launch_bounds__(128) void out_kernel(const float* __restrict__ g2v,
                                                  const float* __restrict__ be2,
                                                  float* __restrict__ out) {
    __shared__ float sstat[20];
    __shared__ float sg[10], sbe[10];
    const int tid = threadIdx.x;
    if (tid < 20) sstat[tid] = g_s2v[tid];
    if (tid < 10) { sg[tid] = g2v[tid]; sbe[tid] = be2[tid]; }
    __syncthreads();

    const int gid = blockIdx.x * blockDim.x + tid;
    #pragma unroll
    for (int o = 0; o < 10; ++o) {
        const float g = sg[o];
        const float h = (g >= 0.0f) ? g_hmax[gid*10 + o] : g_hmin[gid*10 + o];
        const float y = fmaxf(((h - sstat[o]) * sstat[10+o]) * g + sbe[o], 0.0f);
        out[gid*10 + o] = y;
    }
}

// ---------------------------------------------------------------------------
extern "C" void kernel_launch(void* const* d_in, const int* in_sizes, int n_in,
                              void* d_out, int out_size) {
    (void)in_sizes; (void)n_in; (void)out_size;
    const float* x   = (const float*)d_in[0];
    const float* W1  = (const float*)d_in[1];
    const float* b1  = (const float*)d_in[2];
    const float* g1  = (const float*)d_in[3];
    const float* be1 = (const float*)d_in[4];
    const float* W2  = (const float*)d_in[5];
    const float* b2  = (const float*)d_in[6];
    const float* g2  = (const float*)d_in[7];
    const float* be2 = (const float*)d_in[8];
    float* out = (float*)d_out;

    const int smem1 = 4 * NN * 4 + 8 * QW * CAP * 4 + QB * 9 * 4;
    cudaFuncSetAttribute(knn_kernel, cudaFuncAttributeMaxDynamicSharedMemorySize, smem1);

    dim3 grid1(NN / QB, BB);
    knn_kernel<<<grid1, 256, smem1>>>(x, W1, b1);
    stats_kernel<<<1, 640>>>(0, NBP);
    mlp_kernel<<<NBF, 128>>>(g1, be1, W1, b1, W2, b2);
    stats_kernel<<<1, 640>>>(1, NBF);
    out_kernel<<<NPTS/128, 128>>>(g2, be2, out);
}